// round 17
// baseline (speedup 1.0000x reference)
#include <cuda_runtime.h>
#include <cuda_fp16.h>
#include <math_constants.h>
#include <cstdint>

// Problem constants
#define NLAG   12
#define NB     32
#define NN     1200
#define MROWS  1152          // 3 * NLAG * NB
#define KDIM   1200
#define KP     1216          // K padded to 19*64
#define NP     1280          // B storage width (padded)

// GEMM tiling: CTA 128m x 80n, BK=64, 256 threads (8 warps = 4m x 2n, 32x40)
#define BK      64
#define NCHUNK  (KP / BK)    // 19
#define AROWB   144
#define BROWB   176
#define A_TILE  (128 * AROWB)    // 18432
#define B_TILE  (64 * BROWB)     // 11264
#define OFF_A0  0
#define OFF_B0  A_TILE
#define STAGE   (A_TILE + B_TILE)   // 29696
#define NSTAGES 3
#define NUNITS  1664

// Scratch (device globals; no allocation allowed)
__device__ __align__(16) __half g_A0[MROWS * KP];
__device__ __align__(16) __half g_B0[KP * NP];    // k-major
__device__ __align__(16) float g_C[MROWS * NN];
__device__ float g_belta[NLAG];
__device__ float g_c2[NLAG];
__device__ float g_pf[NLAG];

// ---------------------------------------------------------------------------
__device__ __forceinline__ uint32_t smem_u32(const void* p) {
    uint32_t a;
    asm("{ .reg .u64 t; cvta.to.shared.u64 t, %1; cvt.u32.u64 %0, t; }"
        : "=r"(a) : "l"(p));
    return a;
}

#define LDSM4(r, addr)                                                      \
    asm volatile("ldmatrix.sync.aligned.m8n8.x4.shared.b16 "                \
                 "{%0, %1, %2, %3}, [%4];"                                  \
                 : "=r"((r)[0]), "=r"((r)[1]), "=r"((r)[2]), "=r"((r)[3])   \
                 : "r"(addr))
#define LDSM4T(r, addr)                                                     \
    asm volatile("ldmatrix.sync.aligned.m8n8.x4.trans.shared.b16 "          \
                 "{%0, %1, %2, %3}, [%4];"                                  \
                 : "=r"((r)[0]), "=r"((r)[1]), "=r"((r)[2]), "=r"((r)[3])   \
                 : "r"(addr))
#define LDSM2T(r, addr)                                                     \
    asm volatile("ldmatrix.sync.aligned.m8n8.x2.trans.shared.b16 "          \
                 "{%0, %1}, [%2];"                                          \
                 : "=r"((r)[0]), "=r"((r)[1]) : "r"(addr))

#define MMA_F16(c, a, bb0, bb1)                                             \
    asm volatile("mma.sync.aligned.m16n8k16.row.col.f32.f16.f16.f32 "       \
                 "{%0, %1, %2, %3}, {%4, %5, %6, %7}, {%8, %9}, "           \
                 "{%0, %1, %2, %3};"                                        \
                 : "+f"((c)[0]), "+f"((c)[1]), "+f"((c)[2]), "+f"((c)[3])   \
                 : "r"((a)[0]), "r"((a)[1]), "r"((a)[2]), "r"((a)[3]),      \
                   "r"(bb0), "r"(bb1))

#define CP_ASYNC16(dst, src)                                                \
    asm volatile("cp.async.cg.shared.global [%0], [%1], 16;"                \
                 :: "r"(dst), "l"(__cvta_generic_to_global(src)))
#define CP_COMMIT() asm volatile("cp.async.commit_group;" ::: "memory")
#define CP_WAIT1()  asm volatile("cp.async.wait_group 1;" ::: "memory")
#define CP_WAIT0()  asm volatile("cp.async.wait_group 0;" ::: "memory")

// ---------------------------------------------------------------------------
__device__ __forceinline__ float gamma_fn(float x) {
    if (x > 0.f) return expf(lgammaf(x));
    return CUDART_PI_F / (sinf(CUDART_PI_F * x) * expf(lgammaf(1.f - x)));
}

// Single-instruction pack of two f32 into one f16x2 register (lo, hi order).
__device__ __forceinline__ uint32_t cvt2h(float lo, float hi) {
    uint32_t r;
    asm("cvt.rn.f16x2.f32 %0, %1, %2;" : "=r"(r) : "f"(hi), "f"(lo));
    return r;
}

// Pack 8 consecutive floats (two float4) into one uint4 of fp16.
__device__ __forceinline__ uint4 pack8h(float4 a, float4 b) {
    uint4 r;
    r.x = cvt2h(a.x, a.y);
    r.y = cvt2h(a.z, a.w);
    r.z = cvt2h(b.x, b.y);
    r.w = cvt2h(b.z, b.w);
    return r;
}

// ---------------------------------------------------------------------------
// Fused prep, 8-element-per-thread granularity.
//  [0, R0u)  : A slice rows [0,384): 2 float4 loads -> uint4 fp16 store
//  [R0u,+R1) : train_init gather (unchanged; small)
//  [..,+R2u) : zero-fill k padding rows [384,1152), uint4
//  [..,+R3u) : B pack (k-major fp16), 8 elems/thread
// ---------------------------------------------------------------------------
#define R0U (384 * KP / 8)                 // 58368
#define R1U (NB * NN / 2)                  // 19200
#define R2U (768 * (KP - KDIM) / 8)        // 1536
#define R3U (KP * NP / 8)                  // 194560
#define PREP_TOTAL (R0U + R1U + R2U + R3U)

__global__ void prep_kernel(const float* __restrict__ A,
                            const float* __restrict__ WW,
                            const float* __restrict__ train_init,
                            const float* __restrict__ alpha,
                            const float* __restrict__ fract) {
    int idx = blockIdx.x * blockDim.x + threadIdx.x;

    if (blockIdx.x == 0 && threadIdx.x < NLAG) {
        int lag = threadIdx.x;
        float a   = alpha[lag];
        float f   = fract[lag];
        float ga1 = gamma_fn(a + 1.f);
        float gm2 = gamma_fn(a - 2.f);
        float belta = 1.f
                    + ga1 / gamma_fn(a)
                    + ga1 / (2.f * gamma_fn(a - 1.f))
                    + ga1 / (6.f * gm2);
        g_belta[lag] = belta;
        g_c2[lag]    = ga1 / (6.f * gm2);
        g_pf[lag]    = 2.f * powf(3.f, f);
    }

    if (idx < R0U) {
        int r = idx / (KP / 8);
        int k = (idx - r * (KP / 8)) * 8;      // KDIM % 8 == 0: no straddle
        float4 a = make_float4(0.f, 0.f, 0.f, 0.f), b = a;
        if (k < KDIM) {
            const float4* src = reinterpret_cast<const float4*>(&A[r * KDIM + k]);
            a = src[0]; b = src[1];
        }
        reinterpret_cast<uint4*>(g_A0)[idx] = pack8h(a, b);
    } else if (idx < R0U + R1U) {
        int p = idx - R0U;
        int b = p / (NN / 2);
        int i = (p - b * (NN / 2)) * 2;
        const float4* ti4 = reinterpret_cast<const float4*>(
            train_init + (size_t)(b * NN + i) * 26);
        float buf[52];
#pragma unroll
        for (int q = 0; q < 13; q++) {
            float4 v = ti4[q];
            buf[q * 4 + 0] = v.x; buf[q * 4 + 1] = v.y;
            buf[q * 4 + 2] = v.z; buf[q * 4 + 3] = v.w;
        }
#pragma unroll
        for (int j = 0; j < 13; j++) {
            uint32_t h = cvt2h(buf[2 * j + 1], buf[26 + 2 * j + 1]);
            if (j >= 1) {
                int row = 384 + (j - 1) * NB + b;
                *reinterpret_cast<uint32_t*>(&g_A0[(size_t)row * KP + i]) = h;
            }
            if (j <= 11) {
                int row = 768 + j * NB + b;
                *reinterpret_cast<uint32_t*>(&g_A0[(size_t)row * KP + i]) = h;
            }
        }
    } else if (idx < R0U + R1U + R2U) {
        int p = idx - R0U - R1U;
        int padw = (KP - KDIM) / 8;            // 2 units per row
        int row = 384 + p / padw;
        int k   = KDIM + (p % padw) * 8;
        reinterpret_cast<uint4*>(&g_A0[(size_t)row * KP + k])[0] =
            make_uint4(0u, 0u, 0u, 0u);
    } else if (idx < PREP_TOTAL) {
        int p = idx - R0U - R1U - R2U;
        int k = p / (NP / 8);
        int n = (p - k * (NP / 8)) * 8;        // NN % 8 == 0: no straddle
        float4 a = make_float4(0.f, 0.f, 0.f, 0.f), b = a;
        if (k < KDIM && n < NN) {
            const float4* src = reinterpret_cast<const float4*>(&WW[k * NN + n]);
            a = src[0]; b = src[1];
        }
        reinterpret_cast<uint4*>(g_B0)[p] = pack8h(a, b);
    }
}

// ---------------------------------------------------------------------------
// cp.async issue for one chunk: B 64x160B (640 units); A 128x128B (1024 units)
// ---------------------------------------------------------------------------
__device__ __forceinline__ void issue_chunk(uint32_t stage, int m0, int n0,
                                            int k0, int tid) {
#pragma unroll
    for (int i = 0; i < 7; i++) {
        int u = tid + i * 256;
        if (u < NUNITS) {
            uint32_t dst;
            const __half* src;
            if (u < 640) {
                int row = u / 10;
                int seg = u - row * 10;
                src = g_B0 + (size_t)(k0 + row) * NP + n0 + seg * 8;
                dst = stage + OFF_B0 + row * BROWB + seg * 16;
            } else {
                int v   = u - 640;
                int row = v >> 3;
                int seg = v & 7;
                src = g_A0 + (size_t)(m0 + row) * KP + k0 + seg * 8;
                dst = stage + OFF_A0 + row * AROWB + seg * 16;
            }
            CP_ASYNC16(dst, src);
        }
    }
}

// Fragment loader for one k-step
#define LOAD_FRAGS(buf, stage, ks)                                          \
    do {                                                                    \
        LDSM4(A0f[buf], (stage) + OFF_A0 + a_off + (ks) * 32);              \
        LDSM4(A1f[buf], (stage) + OFF_A0 + a_off + 16 * AROWB + (ks) * 32); \
        LDSM4T(&B0r[buf][0], (stage) + OFF_B0 + b4_off + (ks) * 16 * BROWB);\
        LDSM4T(&B0r[buf][4], (stage) + OFF_B0 + b4_off + 32 + (ks) * 16 * BROWB); \
        LDSM2T(&B0r[buf][8], (stage) + OFF_B0 + b2_off + (ks) * 16 * BROWB);\
    } while (0)

// ---------------------------------------------------------------------------
// fp16 HMMA GEMM with register fragment double-buffering (R16 body).
// CTA 128x80, 8 warps (32m x 40n each), BK=64, 3-stage cp.async pipeline.
// Grid (15, 9) = 135 CTAs, one wave.
// ---------------------------------------------------------------------------
__global__ __launch_bounds__(256)
void gemm_mma_kernel() {
    extern __shared__ __align__(16) char smem[];
    const uint32_t sb = smem_u32(smem);
    const int tid  = threadIdx.x;
    const int lane = tid & 31;
    const int wid  = tid >> 5;
    const int wm   = wid & 3;
    const int wn   = wid >> 2;
    const int m0   = blockIdx.y * 128;
    const int n0   = blockIdx.x * 80;

    const int j = lane >> 3, rr = lane & 7;
    const uint32_t a_off  = (uint32_t)((wm * 32 + (j & 1) * 8 + rr) * AROWB + (j >> 1) * 16);
    const uint32_t b4_off = (uint32_t)(((j & 1) * 8 + rr) * BROWB + (j >> 1) * 16 + wn * 80);
    const uint32_t b2_off = (uint32_t)(((j & 1) * 8 + rr) * BROWB + wn * 80 + 64);

    float acc[2][5][4];
#pragma unroll
    for (int mf = 0; mf < 2; mf++)
#pragma unroll
        for (int f = 0; f < 5; f++)
#pragma unroll
            for (int e = 0; e < 4; e++) acc[mf][f][e] = 0.f;

    issue_chunk(sb + 0 * STAGE, m0, n0, 0, tid);
    CP_COMMIT();
    issue_chunk(sb + 1 * STAGE, m0, n0, BK, tid);
    CP_COMMIT();

    uint32_t A0f[2][4], A1f[2][4], B0r[2][10];

    int cur = 0, nx2 = 2;
    for (int c = 0; c < NCHUNK; c++) {
        if (c + 1 < NCHUNK) CP_WAIT1(); else CP_WAIT0();
        __syncthreads();

        if (c + 2 < NCHUNK) {
            issue_chunk(sb + (uint32_t)nx2 * STAGE, m0, n0, (c + 2) * BK, tid);
            CP_COMMIT();
        }

        const uint32_t stage = sb + (uint32_t)cur * STAGE;

        LOAD_FRAGS(0, stage, 0);
#pragma unroll
        for (int ks = 0; ks < 4; ks++) {
            const int pf = ks & 1;
            if (ks < 3) LOAD_FRAGS(pf ^ 1, stage, ks + 1);
#pragma unroll
            for (int f = 0; f < 5; f++) {
                MMA_F16(acc[0][f], A0f[pf], B0r[pf][2 * f], B0r[pf][2 * f + 1]);
                MMA_F16(acc[1][f], A1f[pf], B0r[pf][2 * f], B0r[pf][2 * f + 1]);
            }
        }

        cur = (cur + 1 == NSTAGES) ? 0 : cur + 1;
        nx2 = (nx2 + 1 == NSTAGES) ? 0 : nx2 + 1;
    }

    // Store with fused tanh(-x); cols always < 1200 (grid.x*80 == NN).
    const int gid = lane >> 2, tig = lane & 3;
#pragma unroll
    for (int mf = 0; mf < 2; mf++) {
        const int row = m0 + wm * 32 + mf * 16 + gid;
        float* c0p = &g_C[(size_t)row * NN];
        float* c1p = &g_C[(size_t)(row + 8) * NN];
#pragma unroll
        for (int f = 0; f < 5; f++) {
            int col = n0 + wn * 40 + f * 8 + tig * 2;
            float2 lo, hi;
            lo.x = tanhf(-acc[mf][f][0]);
            lo.y = tanhf(-acc[mf][f][1]);
            hi.x = tanhf(-acc[mf][f][2]);
            hi.y = tanhf(-acc[mf][f][3]);
            *reinterpret_cast<float2*>(c0p + col) = lo;
            *reinterpret_cast<float2*>(c1p + col) = hi;
        }
    }
}

// ---------------------------------------------------------------------------
// Final combine, 8 outputs/thread:
// out = lambd/belta * ( pf*OUT + 3*l*(A0NEW + c2*ANOLD) )
// ---------------------------------------------------------------------------
__global__ void epilogue_kernel(const float* __restrict__ lambd,
                                const float* __restrict__ l,
                                float* __restrict__ out) {
    int idx = blockIdx.x * blockDim.x + threadIdx.x;
    const int total8 = NB * NLAG * (NN / 8);   // 57600
    if (idx >= total8) return;
    int j8  = (idx % (NN / 8)) * 8;
    int lag = (idx / (NN / 8)) % NLAG;
    int b   = idx / ((NN / 8) * NLAG);
    int jm  = j8 % 200;                        // 200 % 8 == 0: jm+7 < 200

    int r = lag * NB + b;
    const float4* o4p = reinterpret_cast<const float4*>(&g_C[(size_t)r * NN + j8]);
    const float4* a4p = reinterpret_cast<const float4*>(&g_C[(size_t)(384 + r) * NN + j8]);
    const float4* n4p = reinterpret_cast<const float4*>(&g_C[(size_t)(768 + r) * NN + j8]);
    const float4* lamp = reinterpret_cast<const float4*>(&lambd[lag * 200 + jm]);
    const float4* lvp  = reinterpret_cast<const float4*>(&l[lag * 200 + jm]);
    float4* outp = reinterpret_cast<float4*>(&out[((size_t)b * NLAG + lag) * NN + j8]);

    float ib = 1.f / g_belta[lag];
    float pf = g_pf[lag];
    float c2 = g_c2[lag];

#pragma unroll
    for (int h = 0; h < 2; h++) {
        float4 o4 = o4p[h], a4 = a4p[h], n4 = n4p[h];
        float4 lam = lamp[h], lv = lvp[h];
        float4 o;
        o.x = lam.x * ib * (pf * o4.x + 3.f * lv.x * (a4.x + c2 * n4.x));
        o.y = lam.y * ib * (pf * o4.y + 3.f * lv.y * (a4.y + c2 * n4.y));
        o.z = lam.z * ib * (pf * o4.z + 3.f * lv.z * (a4.z + c2 * n4.z));
        o.w = lam.w * ib * (pf * o4.w + 3.f * lv.w * (a4.w + c2 * n4.w));
        outp[h] = o;
    }
}

// ---------------------------------------------------------------------------
extern "C" void kernel_launch(void* const* d_in, const int* in_sizes, int n_in,
                              void* d_out, int out_size) {
    const float* A          = (const float*)d_in[0];
    const float* WW         = (const float*)d_in[1];
    const float* train_init = (const float*)d_in[2];
    const float* alpha      = (const float*)d_in[3];
    const float* fract      = (const float*)d_in[4];
    const float* lambd      = (const float*)d_in[5];
    const float* l          = (const float*)d_in[6];
    float* out = (float*)d_out;

    cudaFuncSetAttribute(gemm_mma_kernel,
                         cudaFuncAttributeMaxDynamicSharedMemorySize,
                         NSTAGES * STAGE);

    prep_kernel<<<(PREP_TOTAL + 255) / 256, 256>>>(A, WW, train_init, alpha, fract);

    dim3 ggrid(NN / 80, MROWS / 128);             // (15, 9) = 135 CTAs, one wave
    gemm_mma_kernel<<<ggrid, 256, NSTAGES * STAGE>>>();

    const int total8 = NB * NLAG * (NN / 8);
    epilogue_kernel<<<(total8 + 255) / 256, 256>>>(lambd, l, out);
}